// round 15
// baseline (speedup 1.0000x reference)
#include <cuda_runtime.h>

#define N_   64
#define C_   128
#define T_   2048
#define EPS_ 1e-5f

#define PARTW  8
#define NPART  16384     // 1024 blocks * 2 warps-per-quarter * 8 lanes

__device__ float2 g_psq[C_][NPART];   // {sum, sumsq}

// smem tile: 136 rows (ch -4..131, pads zero) x 160 t (t0-16 .. t0+143)
#define ROWL   160
#define NROWS  136
#define TILE_F (NROWS * ROWL)         // 21760 floats
#define SW_OFF TILE_F                 // weights after tile
#define SMEM_FLOATS (TILE_F + C_ * 12)
#define SMEM_BYTES  (SMEM_FLOATS * 4) // 93.2 KB

__global__ void __launch_bounds__(256, 2)
conv_kernel(const float* __restrict__ x, const float* __restrict__ cw,
            float* __restrict__ out)
{
    extern __shared__ float smem[];
    float* sx = smem;
    float* sw = smem + SW_OFF;

    const int tid    = threadIdx.x;
    const int tchunk = blockIdx.x;     // 0..15
    const int n      = blockIdx.y;     // 0..63
    const int t0     = tchunk * 128;

    // stage weights (padded rows of 12 for float4 loads)
    for (int i = tid; i < C_ * 9; i += 256) {
        int r = i / 9, s = i - r * 9;
        sw[r * 12 + s] = cw[i];
    }

    const float* xn = x + (size_t)n * C_ * T_;

    // stage x tile: row r = channel r-4, col j = t0-16+j; zero pads/OOB
    #pragma unroll 4
    for (int idx = tid; idx < TILE_F / 4; idx += 256) {
        const int r  = idx / 40;
        const int c4 = idx - r * 40;
        const int ch = r - 4;
        float4 v = make_float4(0.f, 0.f, 0.f, 0.f);
        if (ch >= 0 && ch < C_) {
            const int t4 = t0 - 16 + 4 * c4;
            const float* src = xn + ch * T_ + t4;
            if (t4 >= 0 && t4 + 3 < T_) {
                v = *(const float4*)src;
            } else {
                if (t4     >= 0 && t4     < T_) v.x = src[0];
                if (t4 + 1 >= 0 && t4 + 1 < T_) v.y = src[1];
                if (t4 + 2 >= 0 && t4 + 2 < T_) v.z = src[2];
                if (t4 + 3 >= 0 && t4 + 3 < T_) v.w = src[3];
            }
        }
        *(float4*)(sx + r * ROWL + 4 * c4) = v;
    }
    __syncthreads();

    // ---- compute: thread = 2 adjacent t-cols x 32-channel quarter ----
    const int tl   = 2 * (tid & 63);       // local t (even)
    const int cq   = (tid >> 6) * 32;      // quarter base channel
    const int warp = tid >> 5, lane = tid & 31;
    const int bid8 = ((n * 16 + tchunk) * 2 + (warp & 1)) * PARTW;
    float* ot = out + (size_t)n * C_ * T_ + t0 + tl;

    // shift for channel cg, sh(cg) = cg mod 9 - 4, tracked incrementally.
    int sh     = (cq + 5) % 9 - 4;         // sh for cg = cq-4
    int rowoff = cq * ROWL;                // smem row of cg = cq-4

    float y0[16], y1[16];
    #pragma unroll
    for (int k = 0; k < 16; ++k) { y0[k] = 0.f; y1[k] = 0.f; }

    #pragma unroll
    for (int jj = 0; jj <= 40; ++jj) {
        // load channel cg = cq-4+jj into ring slot (cg & 15)
        if (jj <= 39) {
            const int m = (jj + 12) & 15;
            const int a = rowoff + 16 - sh + tl;
            y0[m] = sx[a];
            y1[m] = sx[a + 1];
            rowoff += ROWL;
            sh = (sh == 4) ? -4 : sh + 1;
        }
        // emit output channel r = cq + jj - 9 (newest dep loaded at jj-1)
        if (jj >= 9) {
            const int r = cq + jj - 9;
            const float4 wA = *(const float4*)(sw + r * 12);
            const float4 wB = *(const float4*)(sw + r * 12 + 4);
            const float  w8 = sw[r * 12 + 8];
            const int sb = (jj + 3) & 15;          // slot of y[r-4]
            float p0 = 0.f, p1 = 0.f, p2 = 0.f;
            float q0 = 0.f, q1 = 0.f, q2 = 0.f;
            #define SL(s) ((sb + (s)) & 15)
            p0 = fmaf(wA.x, y0[SL(0)], p0); q0 = fmaf(wA.x, y1[SL(0)], q0);
            p1 = fmaf(wA.y, y0[SL(1)], p1); q1 = fmaf(wA.y, y1[SL(1)], q1);
            p2 = fmaf(wA.z, y0[SL(2)], p2); q2 = fmaf(wA.z, y1[SL(2)], q2);
            p0 = fmaf(wA.w, y0[SL(3)], p0); q0 = fmaf(wA.w, y1[SL(3)], q0);
            p1 = fmaf(wB.x, y0[SL(4)], p1); q1 = fmaf(wB.x, y1[SL(4)], q1);
            p2 = fmaf(wB.y, y0[SL(5)], p2); q2 = fmaf(wB.y, y1[SL(5)], q2);
            p0 = fmaf(wB.z, y0[SL(6)], p0); q0 = fmaf(wB.z, y1[SL(6)], q0);
            p1 = fmaf(wB.w, y0[SL(7)], p1); q1 = fmaf(wB.w, y1[SL(7)], q1);
            p2 = fmaf(w8,   y0[SL(8)], p2); q2 = fmaf(w8,   y1[SL(8)], q2);
            #undef SL
            const float a0 = (p0 + p1) + p2;
            const float a1 = (q0 + q1) + q2;

            // raw conv store (adjacent t pair)
            *(float2*)(ot + r * T_) = make_float2(a0, a1);

            // stats partials
            float s_ = a0 + a1;
            float q_ = fmaf(a0, a0, a1 * a1);
            s_ += __shfl_xor_sync(0xffffffffu, s_, 16);
            q_ += __shfl_xor_sync(0xffffffffu, q_, 16);
            s_ += __shfl_xor_sync(0xffffffffu, s_, 8);
            q_ += __shfl_xor_sync(0xffffffffu, q_, 8);
            if (lane < PARTW)
                g_psq[r][bid8 + lane] = make_float2(s_, q_);
        }
    }
}

// Fused finalize + normalize, grid (C_, 4).
// Each block redundantly reduces its channel's partials (L2-resident),
// then normalizes 16 of the 64 n-rows in-place.
__global__ void __launch_bounds__(512)
finalize_normalize_kernel(const float* __restrict__ gamma,
                          const float* __restrict__ beta,
                          float4* __restrict__ out)
{
    __shared__ float rs[512], rq[512];
    __shared__ float s_sc, s_bi;
    const int c   = blockIdx.x;
    const int g   = blockIdx.y;     // 0..3
    const int tid = threadIdx.x;

    float s = 0.f, q = 0.f;
    #pragma unroll 8
    for (int j = tid; j < NPART; j += 512) {
        const float2 v = g_psq[c][j];
        s += v.x;
        q += v.y;
    }
    rs[tid] = s; rq[tid] = q;
    __syncthreads();
    #pragma unroll
    for (int off = 256; off > 0; off >>= 1) {
        if (tid < off) { rs[tid] += rs[tid + off]; rq[tid] += rq[tid + off]; }
        __syncthreads();
    }
    if (tid == 0) {
        const float invNT = 1.f / (float)(N_ * T_);
        const float m   = rs[0] * invNT;
        const float v   = rq[0] * invNT - m * m;
        const float inv = rsqrtf(v + EPS_);
        const float sc  = gamma[c] * inv;
        s_sc = sc;
        s_bi = beta[c] - m * sc;
    }
    __syncthreads();
    const float sc = s_sc;
    const float bi = s_bi;

    const int TF4 = T_ / 4;   // 512
    #pragma unroll 4
    for (int n = g * 16; n < g * 16 + 16; ++n) {
        const int idx = (n * C_ + c) * TF4 + tid;
        float4 v = out[idx];
        v.x = fmaxf(fmaf(v.x, sc, bi), 0.f);
        v.y = fmaxf(fmaf(v.y, sc, bi), 0.f);
        v.z = fmaxf(fmaf(v.z, sc, bi), 0.f);
        v.w = fmaxf(fmaf(v.w, sc, bi), 0.f);
        out[idx] = v;
    }
}

extern "C" void kernel_launch(void* const* d_in, const int* in_sizes, int n_in,
                              void* d_out, int out_size)
{
    const float* x     = (const float*)d_in[0];
    const float* cw    = (const float*)d_in[1];
    const float* gamma = (const float*)d_in[2];
    const float* beta  = (const float*)d_in[3];
    float* out = (float*)d_out;

    cudaFuncSetAttribute(conv_kernel,
                         cudaFuncAttributeMaxDynamicSharedMemorySize, SMEM_BYTES);

    dim3 cgrid(16, N_);
    conv_kernel<<<cgrid, 256, SMEM_BYTES>>>(x, cw, out);
    dim3 fgrid(C_, 4);
    finalize_normalize_kernel<<<fgrid, 512>>>(gamma, beta, (float4*)out);
}

// round 16
// speedup vs baseline: 1.4800x; 1.4800x over previous
#include <cuda_runtime.h>
#include <cuda_fp16.h>

#define N_   64
#define C_   128
#define T_   2048
#define EPS_ 1e-5f

// Stats writers per channel: 16 tchunks * 64 n * 2 warps = 2048 warps, 4 lanes.
#define PARTW  4
#define NPART  (2048 * PARTW)   // 8192

__device__ float2 g_psq[C_][NPART];          // {sum, sumsq} packed
__device__ __half g_mid[(size_t)N_ * C_ * T_];  // fp16 raw conv intermediate

// Batch-4 pipelined channel sweep (round-14 winner). Ring of 16 slots.
// Iteration k: load channels CLO-4+4k .. CLO-1+4k (8 back-to-back LDGs),
// then (k>=3) compute outputs CLO+4(k-3) .. CLO+3+4(k-3) — newest needed
// channel was loaded at k-1, so compute never waits on a fresh LDG.
// y[c'] = x[c', t - sh(c')], sh(c') = c'%9 - 4.  out[c] = sum_s w[c,s]*y[c-4+s].
// Stats in fp32 BEFORE quantization; raw value stored as fp16.
template<int CLO, int SAFE>
__device__ __forceinline__ void sweep(
    const float* __restrict__ xn, __half* __restrict__ midn,
    const float* __restrict__ sw, int t0, int bid4, int lane)
{
    const float* xt = xn + t0;
    __half* ot = midn + t0;

    float y0[16], y1[16];
    #pragma unroll
    for (int k = 0; k < 16; ++k) { y0[k] = 0.f; y1[k] = 0.f; }

    #pragma unroll
    for (int k = 0; k < 11; ++k) {
        // ---- load group k: 4 channels, 8 independent LDGs ----
        if (k <= 9) {
            #pragma unroll
            for (int u = 0; u < 4; ++u) {
                const int lg = CLO - 4 + 4 * k + u;      // source channel
                const int m  = ((4 * k + u - 4) % 16 + 16) % 16;  // CLO%16==0
                if (lg >= 0 && lg < C_) {
                    const int sh  = ((lg % 9) + 9) % 9 - 4;
                    const int off = lg * T_ - sh;
                    if (SAFE) {
                        y0[m] = xt[off];
                        y1[m] = xt[off + 64];
                    } else {
                        int i = t0 - sh;
                        y0[m] = ((unsigned)i < T_) ? xt[off]      : 0.f; i += 64;
                        y1[m] = ((unsigned)i < T_) ? xt[off + 64] : 0.f;
                    }
                } else if (lg >= C_) {
                    y0[m] = 0.f; y1[m] = 0.f;   // top channel pad
                }
            }
        }
        // ---- compute group k-3: 4 outputs ----
        if (k >= 3) {
            #pragma unroll
            for (int u = 0; u < 4; ++u) {
                const int r = 4 * (k - 3) + u;          // local row [0,32)
                const int c = CLO + r;
                const float4 wA = *(const float4*)(sw + r * 12);
                const float4 wB = *(const float4*)(sw + r * 12 + 4);
                const float  w8 = sw[r * 12 + 8];
                const int sb = ((r - 4) % 16 + 16) % 16;  // slot of y[c-4]
                float p0 = 0.f, p1 = 0.f, p2 = 0.f;
                float q0 = 0.f, q1 = 0.f, q2 = 0.f;
                #define SL(s) ((sb + (s)) & 15)
                p0 = fmaf(wA.x, y0[SL(0)], p0); q0 = fmaf(wA.x, y1[SL(0)], q0);
                p1 = fmaf(wA.y, y0[SL(1)], p1); q1 = fmaf(wA.y, y1[SL(1)], q1);
                p2 = fmaf(wA.z, y0[SL(2)], p2); q2 = fmaf(wA.z, y1[SL(2)], q2);
                p0 = fmaf(wA.w, y0[SL(3)], p0); q0 = fmaf(wA.w, y1[SL(3)], q0);
                p1 = fmaf(wB.x, y0[SL(4)], p1); q1 = fmaf(wB.x, y1[SL(4)], q1);
                p2 = fmaf(wB.y, y0[SL(5)], p2); q2 = fmaf(wB.y, y1[SL(5)], q2);
                p0 = fmaf(wB.z, y0[SL(6)], p0); q0 = fmaf(wB.z, y1[SL(6)], q0);
                p1 = fmaf(wB.w, y0[SL(7)], p1); q1 = fmaf(wB.w, y1[SL(7)], q1);
                p2 = fmaf(w8,   y0[SL(8)], p2); q2 = fmaf(w8,   y1[SL(8)], q2);
                #undef SL
                const float a0 = (p0 + p1) + p2;
                const float a1 = (q0 + q1) + q2;

                // raw conv store as fp16 (normalized later from fp32 stats)
                ot[c * T_     ] = __float2half_rn(a0);
                ot[c * T_ + 64] = __float2half_rn(a1);

                // stats partials (fp32, pre-quantization): 3-stage butterfly
                float s = a0 + a1;
                float q = fmaf(a0, a0, a1 * a1);
                s += __shfl_xor_sync(0xffffffffu, s, 16);
                q += __shfl_xor_sync(0xffffffffu, q, 16);
                s += __shfl_xor_sync(0xffffffffu, s, 8);
                q += __shfl_xor_sync(0xffffffffu, q, 8);
                s += __shfl_xor_sync(0xffffffffu, s, 4);
                q += __shfl_xor_sync(0xffffffffu, q, 4);
                if (lane < PARTW)
                    g_psq[c][bid4 + lane] = make_float2(s, q);
            }
        }
    }
}

__global__ void __launch_bounds__(64, 16)
conv_kernel(const float* __restrict__ x, const float* __restrict__ cw)
{
    __shared__ float sw[32 * 12];

    const int tid    = threadIdx.x;    // 0..63
    const int tchunk = blockIdx.x;     // 0..15 (128 t each)
    const int n      = blockIdx.y;     // 0..63
    const int quart  = blockIdx.z;     // 0..3 (32 channels each)
    const int clo    = quart * 32;

    for (int i = tid; i < 32 * 9; i += 64) {
        int r = i / 9, s = i - r * 9;
        sw[r * 12 + s] = cw[(clo + r) * 9 + s];
    }
    __syncthreads();

    const int t0   = tchunk * 128 + tid;
    const int warp = tid >> 5, lane = tid & 31;
    const int tw   = tchunk * 128 + warp * 32;
    const bool safe = (tw >= 4) && (tw + 31 + 64 + 4 <= T_ - 1);
    const int bid4 = (((n * 16 + tchunk) * 2 + warp) * PARTW);

    const float* xn   = x + (size_t)n * C_ * T_;
    __half*      midn = g_mid + (size_t)n * C_ * T_;

    switch (quart) {
    case 0: if (safe) sweep<0,1>(xn,midn,sw,t0,bid4,lane);  else sweep<0,0>(xn,midn,sw,t0,bid4,lane);  break;
    case 1: if (safe) sweep<32,1>(xn,midn,sw,t0,bid4,lane); else sweep<32,0>(xn,midn,sw,t0,bid4,lane); break;
    case 2: if (safe) sweep<64,1>(xn,midn,sw,t0,bid4,lane); else sweep<64,0>(xn,midn,sw,t0,bid4,lane); break;
    default:if (safe) sweep<96,1>(xn,midn,sw,t0,bid4,lane); else sweep<96,0>(xn,midn,sw,t0,bid4,lane); break;
    }
}

// Fused finalize + normalize, grid (C_, 2).
// Phase 1: each block reduces its channel's 8192 float2 partials (x2 redundant,
// L2-resident) -> scale/bias.
// Phase 2: normalize 32 n-rows: read fp16 intermediate, write fp32 final.
__global__ void __launch_bounds__(512)
finalize_normalize_kernel(const float* __restrict__ gamma,
                          const float* __restrict__ beta,
                          float4* __restrict__ out)
{
    __shared__ float rs[512], rq[512];
    __shared__ float s_sc, s_bi;
    const int c   = blockIdx.x;
    const int g   = blockIdx.y;     // 0..1
    const int tid = threadIdx.x;

    float s = 0.f, q = 0.f;
    #pragma unroll 8
    for (int j = tid; j < NPART; j += 512) {
        const float2 v = g_psq[c][j];
        s += v.x;
        q += v.y;
    }
    rs[tid] = s; rq[tid] = q;
    __syncthreads();
    #pragma unroll
    for (int off = 256; off > 0; off >>= 1) {
        if (tid < off) { rs[tid] += rs[tid + off]; rq[tid] += rq[tid + off]; }
        __syncthreads();
    }
    if (tid == 0) {
        const float invNT = 1.f / (float)(N_ * T_);
        const float m   = rs[0] * invNT;
        const float v   = rq[0] * invNT - m * m;
        const float inv = rsqrtf(v + EPS_);
        const float sc  = gamma[c] * inv;
        s_sc = sc;
        s_bi = beta[c] - m * sc;
    }
    __syncthreads();
    const float sc = s_sc;
    const float bi = s_bi;

    // 32 n-rows; each row = 2048 halves = 256 uint4 chunks of 8 halves.
    #pragma unroll 4
    for (int idx = tid; idx < 32 * 256; idx += 512) {
        const int nl = idx >> 8;           // 0..31
        const int j  = idx & 255;          // uint4 chunk within row
        const int n  = g * 32 + nl;
        const size_t rowh = ((size_t)n * C_ + c) * T_;
        const uint4 h = *(const uint4*)(g_mid + rowh + j * 8);

        const half2* hp = (const half2*)&h;
        float4 v0, v1;
        {
            float2 f0 = __half22float2(hp[0]);
            float2 f1 = __half22float2(hp[1]);
            v0.x = fmaxf(fmaf(f0.x, sc, bi), 0.f);
            v0.y = fmaxf(fmaf(f0.y, sc, bi), 0.f);
            v0.z = fmaxf(fmaf(f1.x, sc, bi), 0.f);
            v0.w = fmaxf(fmaf(f1.y, sc, bi), 0.f);
        }
        {
            float2 f2 = __half22float2(hp[2]);
            float2 f3 = __half22float2(hp[3]);
            v1.x = fmaxf(fmaf(f2.x, sc, bi), 0.f);
            v1.y = fmaxf(fmaf(f2.y, sc, bi), 0.f);
            v1.z = fmaxf(fmaf(f3.x, sc, bi), 0.f);
            v1.w = fmaxf(fmaf(f3.y, sc, bi), 0.f);
        }
        const size_t row4 = ((size_t)n * C_ + c) * (T_ / 4);
        out[row4 + 2 * j    ] = v0;
        out[row4 + 2 * j + 1] = v1;
    }
}

extern "C" void kernel_launch(void* const* d_in, const int* in_sizes, int n_in,
                              void* d_out, int out_size)
{
    const float* x     = (const float*)d_in[0];
    const float* cw    = (const float*)d_in[1];
    const float* gamma = (const float*)d_in[2];
    const float* beta  = (const float*)d_in[3];
    float* out = (float*)d_out;

    dim3 cgrid(16, N_, 4);
    conv_kernel<<<cgrid, 64>>>(x, cw);
    dim3 fgrid(C_, 2);
    finalize_normalize_kernel<<<fgrid, 512>>>(gamma, beta, (float4*)out);
}